// round 5
// baseline (speedup 1.0000x reference)
#include <cuda_runtime.h>
#include <math.h>
#include <float.h>

#define B 4
#define T 8
#define NF 8192
#define C 384
#define H 12
#define TOPK 32
#define D 32
#define HT (H*T)        /* 96 */
#define ROWS (T+NF)     /* 8200 */
#define SCALE 0.17677669529663687f

typedef unsigned long long ull;

// ---------------- scratch (static device globals; no runtime alloc) ----------
__device__ float g_qk[B*HT*C];
__device__ float g_attn[(size_t)B*HT*NF];         // ~12.6MB
__device__ float g_w[B*HT*TOPK];
__device__ int   g_idx[B*HT*TOPK];
__device__ float g_fb[B*T*H*C];

// ---------------- f32x2 helpers (Blackwell packed FFMA) ----------------------
__device__ __forceinline__ ull pack2(float lo, float hi) {
    ull r;
    asm("mov.b64 %0, {%1, %2};" : "=l"(r) : "f"(lo), "f"(hi));
    return r;
}
__device__ __forceinline__ void unpack2(ull v, float& lo, float& hi) {
    asm("mov.b64 {%0, %1}, %2;" : "=f"(lo), "=f"(hi) : "l"(v));
}
__device__ __forceinline__ void fma2(ull& d, ull a, ull b) {
    asm("fma.rn.f32x2 %0, %1, %2, %0;" : "+l"(d) : "l"(a), "l"(b));
}
__device__ __forceinline__ void red_add_v4(float* p, float4 v) {
    asm volatile("red.global.add.v4.f32 [%0], {%1, %2, %3, %4};"
                 :: "l"(p), "f"(v.x), "f"(v.y), "f"(v.z), "f"(v.w) : "memory");
}

// ---------------- kernel 1: zero the output ----------------------------------
__global__ void zero_out_kernel(float4* __restrict__ out, int n4) {
    float4 z = make_float4(0.f, 0.f, 0.f, 0.f);
    for (int i = blockIdx.x * blockDim.x + threadIdx.x; i < n4;
         i += gridDim.x * blockDim.x)
        out[i] = z;
}

// ---------------- kernel 2: fused q projection + qk fold ---------------------
__global__ __launch_bounds__(384) void qqk_kernel(const float* __restrict__ x,
                                                  const float* __restrict__ qs_w,
                                                  const float* __restrict__ kv_w) {
    int b = blockIdx.y, t = blockIdx.x;
    int tid = threadIdx.x;                 // 384
    __shared__ float xs[C];
    __shared__ float qs[C];
    xs[tid] = x[((size_t)b*ROWS + t)*C + tid];
    __syncthreads();

    float acc = 0.f;
    const float* w = qs_w + (size_t)t*C*C + tid;
    #pragma unroll 16
    for (int c = 0; c < C; c++) acc += xs[c] * w[(size_t)c*C];
    qs[tid] = acc;
    __syncthreads();

    const float4* kvr = (const float4*)(kv_w + (size_t)tid*(2*C));
    #pragma unroll
    for (int h = 0; h < H; h++) {
        float s = 0.f;
        #pragma unroll
        for (int d4 = 0; d4 < 8; d4++) {
            float4 kq = kvr[h*8 + d4];
            s += qs[h*D + 4*d4 + 0]*kq.x + qs[h*D + 4*d4 + 1]*kq.y
               + qs[h*D + 4*d4 + 2]*kq.z + qs[h*D + 4*d4 + 3]*kq.w;
        }
        g_qk[(((size_t)b*H + h)*T + t)*C + tid] = s * SCALE;
    }
}

// ---------------- kernel 3: attn = qk . feature^T  (96 x 8192 x 384 / batch) -
// (FROZEN this round — identical to the 229.8us version.)
struct GemmSmem {
    float As[2][96][34];     // [buf][m][k], row stride 34 floats (8B-aligned)
    float Bs[2][32][132];    // [buf][k][n], row stride 132 floats (16B-aligned)
};
#define GEMM_SMEM_BYTES sizeof(GemmSmem)

__global__ __launch_bounds__(256, 2) void attn_gemm_kernel(const float* __restrict__ x) {
    extern __shared__ __align__(16) char smem_raw[];
    GemmSmem& sm = *reinterpret_cast<GemmSmem*>(smem_raw);

    int b  = blockIdx.y;
    int n0 = blockIdx.x * 128;
    int tid = threadIdx.x;
    int tx = tid & 15, ty = tid >> 4;      // m = ty+16i, n = 2tx+32j
    int kk = tid & 31, r  = tid >> 5;      // loader: c = kk, row = r+8i

    const float* qk   = g_qk + (size_t)b*HT*C;
    const float* feat = x + ((size_t)b*ROWS + T)*C;

    ull acc[6][4];
    #pragma unroll
    for (int i = 0; i < 6; i++)
        #pragma unroll
        for (int j = 0; j < 4; j++) acc[i][j] = 0ull;

    float pa[12], pb[16];
    #pragma unroll
    for (int i = 0; i < 12; i++) pa[i] = qk[(size_t)(r + 8*i)*C + kk];
    #pragma unroll
    for (int i = 0; i < 16; i++) pb[i] = feat[(size_t)(n0 + r + 8*i)*C + kk];
    #pragma unroll
    for (int i = 0; i < 12; i++) sm.As[0][r + 8*i][kk] = pa[i];
    #pragma unroll
    for (int i = 0; i < 16; i++) sm.Bs[0][kk][r + 8*i] = pb[i];
    __syncthreads();

    #pragma unroll 1
    for (int tile = 0; tile < 12; tile++) {
        int cur = tile & 1;
        if (tile < 11) {
            int c1 = (tile + 1) * 32;
            #pragma unroll
            for (int i = 0; i < 12; i++) pa[i] = qk[(size_t)(r + 8*i)*C + c1 + kk];
            #pragma unroll
            for (int i = 0; i < 16; i++) pb[i] = feat[(size_t)(n0 + r + 8*i)*C + c1 + kk];
        }
        #pragma unroll
        for (int k = 0; k < 32; k += 2) {
            ull b0[4], b1[4];
            float2 a01[6];
            #pragma unroll
            for (int j = 0; j < 4; j++) {
                b0[j] = *(const ull*)&sm.Bs[cur][k    ][32*j + 2*tx];
                b1[j] = *(const ull*)&sm.Bs[cur][k + 1][32*j + 2*tx];
            }
            #pragma unroll
            for (int i = 0; i < 6; i++)
                a01[i] = *(const float2*)&sm.As[cur][ty + 16*i][k];
            #pragma unroll
            for (int i = 0; i < 6; i++) {
                ull au = pack2(a01[i].x, a01[i].x);
                ull av = pack2(a01[i].y, a01[i].y);
                #pragma unroll
                for (int j = 0; j < 4; j++) {
                    fma2(acc[i][j], au, b0[j]);
                    fma2(acc[i][j], av, b1[j]);
                }
            }
        }
        if (tile < 11) {
            int nxt = cur ^ 1;
            #pragma unroll
            for (int i = 0; i < 12; i++) sm.As[nxt][r + 8*i][kk] = pa[i];
            #pragma unroll
            for (int i = 0; i < 16; i++) sm.Bs[nxt][kk][r + 8*i] = pb[i];
            __syncthreads();
        }
    }

    float* outp = g_attn + (size_t)b*HT*NF;
    #pragma unroll
    for (int i = 0; i < 6; i++)
        #pragma unroll
        for (int j = 0; j < 4; j++) {
            float2 v;
            unpack2(acc[i][j], v.x, v.y);
            *(float2*)&outp[(size_t)(ty + 16*i)*NF + n0 + 32*j + 2*tx] = v;
        }
}

// ---------------- kernel 4: exact top-32 via 4-pass radix select --------------
__device__ __forceinline__ unsigned enc_key(unsigned b) {
    return (b & 0x80000000u) ? ~b : (b | 0x80000000u);
}
__device__ __forceinline__ float dec_key(unsigned u) {
    unsigned b = (u & 0x80000000u) ? (u ^ 0x80000000u) : ~u;
    return __uint_as_float(b);
}

__global__ __launch_bounds__(256) void topk_kernel() {
    int row = blockIdx.x;                  // b*HT + h*T + t
    int tid = threadIdx.x;                 // 256
    int lane = tid & 31, wp = tid >> 5;
    __shared__ unsigned keys[NF];          // 32KB
    __shared__ unsigned hist[256];
    __shared__ unsigned wsuf[8];
    __shared__ unsigned sh_need, sh_prefix;
    __shared__ int cntG;
    __shared__ unsigned candK[TOPK];
    __shared__ int candI[TOPK];
    __shared__ int ri[256];
    __shared__ float outv[TOPK];
    __shared__ int outi[TOPK];

    hist[tid] = 0;
    if (tid == 0) { sh_need = TOPK; sh_prefix = 0; cntG = 0; }
    __syncthreads();

    // load + pass-0 histogram fused
    const uint4* src = (const uint4*)(g_attn + (size_t)row*NF);
    for (int i = tid; i < NF/4; i += 256) {
        uint4 u = src[i];
        unsigned k0 = enc_key(u.x), k1 = enc_key(u.y);
        unsigned k2 = enc_key(u.z), k3 = enc_key(u.w);
        keys[4*i+0] = k0; keys[4*i+1] = k1;
        keys[4*i+2] = k2; keys[4*i+3] = k3;
        atomicAdd(&hist[k0 >> 24], 1u);
        atomicAdd(&hist[k1 >> 24], 1u);
        atomicAdd(&hist[k2 >> 24], 1u);
        atomicAdd(&hist[k3 >> 24], 1u);
    }
    __syncthreads();

    #pragma unroll
    for (int pass = 0; pass < 4; pass++) {
        int shift = 24 - 8*pass;
        if (pass > 0) {
            hist[tid] = 0;
            __syncthreads();
            unsigned pref  = sh_prefix;
            unsigned pmask = 0xFFFFFFFFu << (shift + 8);
            for (int i = tid; i < NF; i += 256) {
                unsigned k = keys[i];
                if ((k & pmask) == pref) atomicAdd(&hist[(k >> shift) & 255], 1u);
            }
            __syncthreads();
        }

        // inclusive suffix sum over 256 bins: warp shuffle + 8-wide combine
        unsigned v = hist[tid];
        unsigned inc = v;
        #pragma unroll
        for (int s = 1; s < 32; s <<= 1) {
            unsigned tv = __shfl_down_sync(0xffffffffu, inc, s);
            if (lane + s < 32) inc += tv;
        }
        if (lane == 0) wsuf[wp] = inc;     // warp-total
        __syncthreads();
        if (tid < 8) {
            unsigned tv = wsuf[tid];
            #pragma unroll
            for (int s = 1; s < 8; s <<= 1) {
                unsigned t2 = __shfl_down_sync(0xffu, tv, s);
                if (tid + s < 8) tv += t2;
            }
            wsuf[tid] = tv;                // suffix over warp-totals
        }
        __syncthreads();
        unsigned incl = inc + (wp < 7 ? wsuf[wp + 1] : 0u);
        unsigned need = sh_need;
        unsigned excl = incl - v;
        if (incl >= need && excl < need) {              // unique thread
            sh_prefix = sh_prefix | ((unsigned)tid << shift);
            sh_need   = need - excl;
        }
        __syncthreads();
    }
    unsigned V = sh_prefix;       // exact value of the 32nd-largest key
    int E = (int)sh_need;         // #ties (== V) needed, smallest indices first

    // collect keys strictly greater than V (exactly TOPK - E of them)
    for (int i = tid; i < NF; i += 256) {
        unsigned k = keys[i];
        if (k > V) { int p = atomicAdd(&cntG, 1); candK[p] = k; candI[p] = i; }
    }
    __syncthreads();
    int G = cntG;

    // ties: take the E smallest indices with key == V
    int last = -1;
    for (int e = 0; e < E; e++) {
        int best = NF;
        for (int i = tid; i < NF; i += 256)
            if (keys[i] == V && i > last && i < best) best = i;
        ri[tid] = best;
        __syncthreads();
        for (int s = 128; s > 0; s >>= 1) {
            if (tid < s) ri[tid] = min(ri[tid], ri[tid + s]);
            __syncthreads();
        }
        int widx = ri[0];
        if (tid == 0) { candK[G + e] = V; candI[G + e] = widx; }
        last = widx;
        __syncthreads();
    }

    // rank-sort the 32 candidates: value desc, index asc
    if (tid < 32) {
        unsigned k = candK[tid];
        int ix = candI[tid];
        ull ck = ((ull)k << 32) | (ull)(0xFFFFFFFFu - (unsigned)ix);
        int rank = 0;
        #pragma unroll
        for (int j = 0; j < 32; j++) {
            ull o = __shfl_sync(0xffffffffu, ck, j);
            rank += (o > ck);
        }
        outv[rank] = dec_key(k);
        outi[rank] = ix;
    }
    __syncwarp();
    if (tid < 32) {
        float m = outv[0];
        float e = expf(outv[tid] - m);
        float sum = e;
        #pragma unroll
        for (int o = 16; o > 0; o >>= 1) sum += __shfl_xor_sync(0xffffffffu, sum, o);
        g_w[row*TOPK + tid]   = e / sum;
        g_idx[row*TOPK + tid] = outi[tid];
    }
}

// ---------------- kernel 5: fused gather (fb) + vectorized sparse scatter ----
// Scatter now stages contributions in smem and issues red.global.add.v4.f32
// (4x fewer reduction lanes than scalar atomicAdd).
__global__ __launch_bounds__(384) void gather_scatter_kernel(const float* __restrict__ x,
                                                             const float* __restrict__ experts_w,
                                                             float* __restrict__ out) {
    int t = blockIdx.x, h = blockIdx.y, b = blockIdx.z;
    int tid = threadIdx.x;                 // 384
    __shared__ float wsh[TOPK];
    __shared__ int   ish[TOPK];
    __shared__ float fsh[TOPK][D];
    __shared__ __align__(16) float sc[4][C];   // staging: 4 k-rows x 384 cols

    int row = (b*H + h)*T + t;
    if (tid < TOPK) {
        wsh[tid] = g_w[row*TOPK + tid];
        ish[tid] = g_idx[row*TOPK + tid];
    }
    __syncthreads();

    const float* feat = x + ((size_t)b*ROWS + T)*C;
    int c = tid;
    int hD = h*D;
    bool mine = (c >= hD) && (c < hD + D);
    int d = c - hD;
    float a = 0.f;
    #pragma unroll
    for (int k = 0; k < TOPK; k++) {
        float v  = feat[(size_t)ish[k]*C + c];
        float wv = wsh[k] * v;
        a += wv;
        if (mine) fsh[k][d] = wv;
    }
    g_fb[(((size_t)b*T + t)*H + h)*C + c] = a;
    __syncthreads();

    // per-thread expert column (kept in registers)
    int o = tid;
    float ecol[D];
    const float* ew = experts_w + ((size_t)t*C + hD)*C + o;
    #pragma unroll
    for (int d2 = 0; d2 < D; d2++) ecol[d2] = ew[(size_t)d2*C];

    float* outb = out + ((size_t)b*ROWS + T)*C;
    int kq = tid / (C/4);                  // 0..3
    int o4 = tid % (C/4);                  // 0..95
    #pragma unroll 1
    for (int g = 0; g < TOPK/4; g++) {
        #pragma unroll
        for (int j = 0; j < 4; j++) {
            int k = g*4 + j;
            float s = 0.f;
            #pragma unroll
            for (int d2 = 0; d2 < D; d2++) s += fsh[k][d2] * ecol[d2];
            sc[j][o] = s;
        }
        __syncthreads();
        float4 v = *(const float4*)&sc[kq][4*o4];
        red_add_v4(&outb[(size_t)ish[g*4 + kq]*C + 4*o4], v);
        __syncthreads();
    }
}

// ---------------- kernel 6: attn_token projection + token_out ----------------
__global__ __launch_bounds__(384) void token_out_kernel(const float* __restrict__ kv_w,
                                                        const float* __restrict__ experts_w,
                                                        float* __restrict__ out) {
    int b = blockIdx.y, t = blockIdx.x;
    int tid = threadIdx.x;                 // 384
    __shared__ float fb[H*C];              // 18KB
    __shared__ float at[C];

    const float* fbg = g_fb + ((size_t)b*T + t)*H*C;
    for (int i = tid; i < H*C; i += 384) fb[i] = fbg[i];
    __syncthreads();

    {
        int h = tid >> 5, d = tid & 31;
        float s = 0.f;
        const float* col = kv_w + C + h*D + d;      // v-half column
        #pragma unroll 8
        for (int c = 0; c < C; c++) s += fb[h*C + c] * col[(size_t)c*(2*C)];
        at[h*D + d] = s;
    }
    __syncthreads();
    {
        float o_acc = 0.f;
        const float* ew = experts_w + (size_t)t*C*C + tid;
        #pragma unroll 8
        for (int c = 0; c < C; c++) o_acc += at[c] * ew[(size_t)c*C];
        out[((size_t)b*ROWS + t)*C + tid] = o_acc;
    }
}

// ---------------- launcher ----------------------------------------------------
extern "C" void kernel_launch(void* const* d_in, const int* in_sizes, int n_in,
                              void* d_out, int out_size) {
    const float* x = nullptr; const float* qs_w = nullptr;
    const float* kv_w = nullptr; const float* experts_w = nullptr;
    for (int i = 0; i < n_in; i++) {
        if (in_sizes[i] == B*ROWS*C)      x = (const float*)d_in[i];
        else if (in_sizes[i] == C*2*C)    kv_w = (const float*)d_in[i];
        else if (in_sizes[i] == T*C*C) {
            if (!qs_w) qs_w = (const float*)d_in[i];
            else       experts_w = (const float*)d_in[i];
        }
    }
    float* out = (float*)d_out;

    cudaFuncSetAttribute(attn_gemm_kernel,
                         cudaFuncAttributeMaxDynamicSharedMemorySize,
                         (int)GEMM_SMEM_BYTES);

    zero_out_kernel<<<1024, 256>>>((float4*)d_out, out_size / 4);
    qqk_kernel<<<dim3(T, B), 384>>>(x, qs_w, kv_w);
    attn_gemm_kernel<<<dim3(NF/128, B), 256, GEMM_SMEM_BYTES>>>(x);
    topk_kernel<<<B*HT, 256>>>();
    gather_scatter_kernel<<<dim3(T, H, B), 384>>>(x, experts_w, out);
    token_out_kernel<<<dim3(T, B), 384>>>(kv_w, experts_w, out);
}

// round 6
// speedup vs baseline: 1.0526x; 1.0526x over previous
#include <cuda_runtime.h>
#include <math.h>
#include <float.h>

#define B 4
#define T 8
#define NF 8192
#define C 384
#define H 12
#define TOPK 32
#define D 32
#define HT (H*T)        /* 96 */
#define ROWS (T+NF)     /* 8200 */
#define SCALE 0.17677669529663687f

typedef unsigned long long ull;
typedef unsigned int uint;

// ---------------- scratch (static device globals; no runtime alloc) ----------
__device__ float g_qk[B*HT*C];
__device__ float g_attn[(size_t)B*HT*NF];         // ~12.6MB
__device__ float g_w[B*HT*TOPK];
__device__ int   g_idx[B*HT*TOPK];
__device__ float g_fb[B*T*H*C];

// ---------------- helpers -----------------------------------------------------
__device__ __forceinline__ void red_add_v4(float* p, float4 v) {
    asm volatile("red.global.add.v4.f32 [%0], {%1, %2, %3, %4};"
                 :: "l"(p), "f"(v.x), "f"(v.y), "f"(v.z), "f"(v.w) : "memory");
}
__device__ __forceinline__ uint to_tf32(float f) {
    uint r;
    asm("cvt.rna.tf32.f32 %0, %1;" : "=r"(r) : "f"(f));
    return r;
}
__device__ __forceinline__ void mma_tf32(float& d0, float& d1, float& d2, float& d3,
                                         uint a0, uint a1, uint a2, uint a3,
                                         uint b0, uint b1) {
    asm("mma.sync.aligned.m16n8k8.row.col.f32.tf32.tf32.f32 "
        "{%0,%1,%2,%3}, {%4,%5,%6,%7}, {%8,%9}, {%0,%1,%2,%3};"
        : "+f"(d0), "+f"(d1), "+f"(d2), "+f"(d3)
        : "r"(a0), "r"(a1), "r"(a2), "r"(a3), "r"(b0), "r"(b1));
}

// ---------------- kernel 1: zero the output ----------------------------------
__global__ void zero_out_kernel(float4* __restrict__ out, int n4) {
    float4 z = make_float4(0.f, 0.f, 0.f, 0.f);
    for (int i = blockIdx.x * blockDim.x + threadIdx.x; i < n4;
         i += gridDim.x * blockDim.x)
        out[i] = z;
}

// ---------------- kernel 2: fused q projection + qk fold ---------------------
__global__ __launch_bounds__(384) void qqk_kernel(const float* __restrict__ x,
                                                  const float* __restrict__ qs_w,
                                                  const float* __restrict__ kv_w) {
    int b = blockIdx.y, t = blockIdx.x;
    int tid = threadIdx.x;                 // 384
    __shared__ float xs[C];
    __shared__ float qs[C];
    xs[tid] = x[((size_t)b*ROWS + t)*C + tid];
    __syncthreads();

    float acc = 0.f;
    const float* w = qs_w + (size_t)t*C*C + tid;
    #pragma unroll 16
    for (int c = 0; c < C; c++) acc += xs[c] * w[(size_t)c*C];
    qs[tid] = acc;
    __syncthreads();

    const float4* kvr = (const float4*)(kv_w + (size_t)tid*(2*C));
    #pragma unroll
    for (int h = 0; h < H; h++) {
        float s = 0.f;
        #pragma unroll
        for (int d4 = 0; d4 < 8; d4++) {
            float4 kq = kvr[h*8 + d4];
            s += qs[h*D + 4*d4 + 0]*kq.x + qs[h*D + 4*d4 + 1]*kq.y
               + qs[h*D + 4*d4 + 2]*kq.z + qs[h*D + 4*d4 + 3]*kq.w;
        }
        g_qk[(((size_t)b*H + h)*T + t)*C + tid] = s * SCALE;
    }
}

// ---------------- kernel 3: attn GEMM via 3xTF32 tensor cores ----------------
// Per batch: M=96 x N=8192 x K=384. Block tile 96x128, 8 warps (2m x 4n),
// warp tile 48x32 = 3 m-tiles x 4 n-tiles of m16n8k8. hi/lo split staged in smem.
struct GemmSmem {
    float Ah[96][36];   // stride 36 -> frag bank = (4g+tig) : conflict-free
    float Al[96][36];
    float Bh[128][36];
    float Bl[128][36];
};
#define GEMM_SMEM_BYTES sizeof(GemmSmem)

__global__ __launch_bounds__(256, 2) void attn_gemm_kernel(const float* __restrict__ x) {
    extern __shared__ __align__(16) char smem_raw[];
    GemmSmem& sm = *reinterpret_cast<GemmSmem*>(smem_raw);

    int b  = blockIdx.y;
    int n0 = blockIdx.x * 128;
    int tid = threadIdx.x;
    int wid = tid >> 5, lane = tid & 31;
    int g = lane >> 2, tig = lane & 3;     // mma fragment coords
    int wm = wid & 1, wn = wid >> 1;       // 2x4 warp grid

    const float* qk   = g_qk + (size_t)b*HT*C;
    const float* feat = x + ((size_t)b*ROWS + T)*C;

    float acc[3][4][4];                    // [mt][nt][frag]
    #pragma unroll
    for (int i = 0; i < 3; i++)
        #pragma unroll
        for (int j = 0; j < 4; j++)
            #pragma unroll
            for (int r = 0; r < 4; r++) acc[i][j][r] = 0.f;

    #pragma unroll 1
    for (int chunk = 0; chunk < 12; chunk++) {
        int c0 = chunk * 32;
        __syncthreads();
        // stage A (96x32) with hi/lo split
        #pragma unroll
        for (int j = 0; j < 12; j++) {
            int idx = tid + j*256;         // 3072 total
            int m = idx >> 5, k = idx & 31;
            float a = qk[(size_t)m*C + c0 + k];
            uint hb = to_tf32(a);
            float hf = __uint_as_float(hb);
            float lo = a - hf;
            sm.Ah[m][k] = hf;
            sm.Al[m][k] = __uint_as_float(to_tf32(lo));
        }
        // stage B (128x32) with hi/lo split
        #pragma unroll
        for (int j = 0; j < 16; j++) {
            int idx = tid + j*256;         // 4096 total
            int n = idx >> 5, k = idx & 31;
            float v = feat[(size_t)(n0 + n)*C + c0 + k];
            uint hb = to_tf32(v);
            float hf = __uint_as_float(hb);
            float lo = v - hf;
            sm.Bh[n][k] = hf;
            sm.Bl[n][k] = __uint_as_float(to_tf32(lo));
        }
        __syncthreads();

        #pragma unroll
        for (int k8 = 0; k8 < 4; k8++) {
            int kc = k8*8 + tig;
            // B fragments for 4 n-tiles
            uint bh[4][2], bl[4][2];
            #pragma unroll
            for (int nt = 0; nt < 4; nt++) {
                int n = wn*32 + nt*8 + g;
                bh[nt][0] = __float_as_uint(sm.Bh[n][kc]);
                bh[nt][1] = __float_as_uint(sm.Bh[n][kc + 4]);
                bl[nt][0] = __float_as_uint(sm.Bl[n][kc]);
                bl[nt][1] = __float_as_uint(sm.Bl[n][kc + 4]);
            }
            // A fragments for 3 m-tiles + MMA
            #pragma unroll
            for (int mt = 0; mt < 3; mt++) {
                int m0 = wm*48 + mt*16;
                uint ah0 = __float_as_uint(sm.Ah[m0 + g    ][kc]);
                uint ah1 = __float_as_uint(sm.Ah[m0 + g + 8][kc]);
                uint ah2 = __float_as_uint(sm.Ah[m0 + g    ][kc + 4]);
                uint ah3 = __float_as_uint(sm.Ah[m0 + g + 8][kc + 4]);
                uint al0 = __float_as_uint(sm.Al[m0 + g    ][kc]);
                uint al1 = __float_as_uint(sm.Al[m0 + g + 8][kc]);
                uint al2 = __float_as_uint(sm.Al[m0 + g    ][kc + 4]);
                uint al3 = __float_as_uint(sm.Al[m0 + g + 8][kc + 4]);
                #pragma unroll
                for (int nt = 0; nt < 4; nt++) {
                    float* d = acc[mt][nt];
                    mma_tf32(d[0], d[1], d[2], d[3],
                             ah0, ah1, ah2, ah3, bh[nt][0], bh[nt][1]);
                    mma_tf32(d[0], d[1], d[2], d[3],
                             ah0, ah1, ah2, ah3, bl[nt][0], bl[nt][1]);
                    mma_tf32(d[0], d[1], d[2], d[3],
                             al0, al1, al2, al3, bh[nt][0], bh[nt][1]);
                }
            }
        }
    }

    // epilogue: D[m][n], frag: d0=(g,2tig) d1=(g,2tig+1) d2=(g+8,..) d3
    float* outp = g_attn + (size_t)b*HT*NF;
    #pragma unroll
    for (int mt = 0; mt < 3; mt++) {
        int m0 = wm*48 + mt*16;
        #pragma unroll
        for (int nt = 0; nt < 4; nt++) {
            int nc = n0 + wn*32 + nt*8 + 2*tig;
            *(float2*)&outp[(size_t)(m0 + g    )*NF + nc] =
                make_float2(acc[mt][nt][0], acc[mt][nt][1]);
            *(float2*)&outp[(size_t)(m0 + g + 8)*NF + nc] =
                make_float2(acc[mt][nt][2], acc[mt][nt][3]);
        }
    }
}

// ---------------- kernel 4: exact top-32 via 4-pass radix select --------------
__device__ __forceinline__ unsigned enc_key(unsigned b) {
    return (b & 0x80000000u) ? ~b : (b | 0x80000000u);
}
__device__ __forceinline__ float dec_key(unsigned u) {
    unsigned b = (u & 0x80000000u) ? (u ^ 0x80000000u) : ~u;
    return __uint_as_float(b);
}

__global__ __launch_bounds__(256) void topk_kernel() {
    int row = blockIdx.x;                  // b*HT + h*T + t
    int tid = threadIdx.x;                 // 256
    int lane = tid & 31, wp = tid >> 5;
    __shared__ unsigned keys[NF];          // 32KB
    __shared__ unsigned hist[256];
    __shared__ unsigned wsuf[8];
    __shared__ unsigned sh_need, sh_prefix;
    __shared__ int cntG;
    __shared__ unsigned candK[TOPK];
    __shared__ int candI[TOPK];
    __shared__ int ri[256];
    __shared__ float outv[TOPK];
    __shared__ int outi[TOPK];

    hist[tid] = 0;
    if (tid == 0) { sh_need = TOPK; sh_prefix = 0; cntG = 0; }
    __syncthreads();

    // load + pass-0 histogram fused
    const uint4* src = (const uint4*)(g_attn + (size_t)row*NF);
    for (int i = tid; i < NF/4; i += 256) {
        uint4 u = src[i];
        unsigned k0 = enc_key(u.x), k1 = enc_key(u.y);
        unsigned k2 = enc_key(u.z), k3 = enc_key(u.w);
        keys[4*i+0] = k0; keys[4*i+1] = k1;
        keys[4*i+2] = k2; keys[4*i+3] = k3;
        atomicAdd(&hist[k0 >> 24], 1u);
        atomicAdd(&hist[k1 >> 24], 1u);
        atomicAdd(&hist[k2 >> 24], 1u);
        atomicAdd(&hist[k3 >> 24], 1u);
    }
    __syncthreads();

    #pragma unroll
    for (int pass = 0; pass < 4; pass++) {
        int shift = 24 - 8*pass;
        if (pass > 0) {
            hist[tid] = 0;
            __syncthreads();
            unsigned pref  = sh_prefix;
            unsigned pmask = 0xFFFFFFFFu << (shift + 8);
            for (int i = tid; i < NF; i += 256) {
                unsigned k = keys[i];
                if ((k & pmask) == pref) atomicAdd(&hist[(k >> shift) & 255], 1u);
            }
            __syncthreads();
        }

        unsigned v = hist[tid];
        unsigned inc = v;
        #pragma unroll
        for (int s = 1; s < 32; s <<= 1) {
            unsigned tv = __shfl_down_sync(0xffffffffu, inc, s);
            if (lane + s < 32) inc += tv;
        }
        if (lane == 0) wsuf[wp] = inc;
        __syncthreads();
        if (tid < 8) {
            unsigned tv = wsuf[tid];
            #pragma unroll
            for (int s = 1; s < 8; s <<= 1) {
                unsigned t2 = __shfl_down_sync(0xffu, tv, s);
                if (tid + s < 8) tv += t2;
            }
            wsuf[tid] = tv;
        }
        __syncthreads();
        unsigned incl = inc + (wp < 7 ? wsuf[wp + 1] : 0u);
        unsigned need = sh_need;
        unsigned excl = incl - v;
        if (incl >= need && excl < need) {
            sh_prefix = sh_prefix | ((unsigned)tid << shift);
            sh_need   = need - excl;
        }
        __syncthreads();
    }
    unsigned V = sh_prefix;
    int E = (int)sh_need;

    for (int i = tid; i < NF; i += 256) {
        unsigned k = keys[i];
        if (k > V) { int p = atomicAdd(&cntG, 1); candK[p] = k; candI[p] = i; }
    }
    __syncthreads();
    int G = cntG;

    int last = -1;
    for (int e = 0; e < E; e++) {
        int best = NF;
        for (int i = tid; i < NF; i += 256)
            if (keys[i] == V && i > last && i < best) best = i;
        ri[tid] = best;
        __syncthreads();
        for (int s = 128; s > 0; s >>= 1) {
            if (tid < s) ri[tid] = min(ri[tid], ri[tid + s]);
            __syncthreads();
        }
        int widx = ri[0];
        if (tid == 0) { candK[G + e] = V; candI[G + e] = widx; }
        last = widx;
        __syncthreads();
    }

    if (tid < 32) {
        unsigned k = candK[tid];
        int ix = candI[tid];
        ull ck = ((ull)k << 32) | (ull)(0xFFFFFFFFu - (unsigned)ix);
        int rank = 0;
        #pragma unroll
        for (int j = 0; j < 32; j++) {
            ull o = __shfl_sync(0xffffffffu, ck, j);
            rank += (o > ck);
        }
        outv[rank] = dec_key(k);
        outi[rank] = ix;
    }
    __syncwarp();
    if (tid < 32) {
        float m = outv[0];
        float e = expf(outv[tid] - m);
        float sum = e;
        #pragma unroll
        for (int o = 16; o > 0; o >>= 1) sum += __shfl_xor_sync(0xffffffffu, sum, o);
        g_w[row*TOPK + tid]   = e / sum;
        g_idx[row*TOPK + tid] = outi[tid];
    }
}

// ---------------- kernel 5: fused gather (fb) + vectorized sparse scatter ----
__global__ __launch_bounds__(384) void gather_scatter_kernel(const float* __restrict__ x,
                                                             const float* __restrict__ experts_w,
                                                             float* __restrict__ out) {
    int t = blockIdx.x, h = blockIdx.y, b = blockIdx.z;
    int tid = threadIdx.x;                 // 384
    __shared__ float wsh[TOPK];
    __shared__ int   ish[TOPK];
    __shared__ float fsh[TOPK][D];
    __shared__ __align__(16) float sc[4][C];

    int row = (b*H + h)*T + t;
    if (tid < TOPK) {
        wsh[tid] = g_w[row*TOPK + tid];
        ish[tid] = g_idx[row*TOPK + tid];
    }
    __syncthreads();

    const float* feat = x + ((size_t)b*ROWS + T)*C;
    int c = tid;
    int hD = h*D;
    bool mine = (c >= hD) && (c < hD + D);
    int d = c - hD;
    float a = 0.f;
    #pragma unroll
    for (int k = 0; k < TOPK; k++) {
        float v  = feat[(size_t)ish[k]*C + c];
        float wv = wsh[k] * v;
        a += wv;
        if (mine) fsh[k][d] = wv;
    }
    g_fb[(((size_t)b*T + t)*H + h)*C + c] = a;
    __syncthreads();

    int o = tid;
    float ecol[D];
    const float* ew = experts_w + ((size_t)t*C + hD)*C + o;
    #pragma unroll
    for (int d2 = 0; d2 < D; d2++) ecol[d2] = ew[(size_t)d2*C];

    float* outb = out + ((size_t)b*ROWS + T)*C;
    int kq = tid / (C/4);
    int o4 = tid % (C/4);
    #pragma unroll 1
    for (int gI = 0; gI < TOPK/4; gI++) {
        #pragma unroll
        for (int j = 0; j < 4; j++) {
            int k = gI*4 + j;
            float s = 0.f;
            #pragma unroll
            for (int d2 = 0; d2 < D; d2++) s += fsh[k][d2] * ecol[d2];
            sc[j][o] = s;
        }
        __syncthreads();
        float4 v = *(const float4*)&sc[kq][4*o4];
        red_add_v4(&outb[(size_t)ish[gI*4 + kq]*C + 4*o4], v);
        __syncthreads();
    }
}

// ---------------- kernel 6: attn_token projection + token_out ----------------
__global__ __launch_bounds__(384) void token_out_kernel(const float* __restrict__ kv_w,
                                                        const float* __restrict__ experts_w,
                                                        float* __restrict__ out) {
    int b = blockIdx.y, t = blockIdx.x;
    int tid = threadIdx.x;                 // 384
    __shared__ float fb[H*C];              // 18KB
    __shared__ float at[C];

    const float* fbg = g_fb + ((size_t)b*T + t)*H*C;
    for (int i = tid; i < H*C; i += 384) fb[i] = fbg[i];
    __syncthreads();

    {
        int h = tid >> 5, d = tid & 31;
        float s = 0.f;
        const float* col = kv_w + C + h*D + d;
        #pragma unroll 8
        for (int c = 0; c < C; c++) s += fb[h*C + c] * col[(size_t)c*(2*C)];
        at[h*D + d] = s;
    }
    __syncthreads();
    {
        float o_acc = 0.f;
        const float* ew = experts_w + (size_t)t*C*C + tid;
        #pragma unroll 8
        for (int c = 0; c < C; c++) o_acc += at[c] * ew[(size_t)c*C];
        out[((size_t)b*ROWS + t)*C + tid] = o_acc;
    }
}

// ---------------- launcher ----------------------------------------------------
extern "C" void kernel_launch(void* const* d_in, const int* in_sizes, int n_in,
                              void* d_out, int out_size) {
    const float* x = nullptr; const float* qs_w = nullptr;
    const float* kv_w = nullptr; const float* experts_w = nullptr;
    for (int i = 0; i < n_in; i++) {
        if (in_sizes[i] == B*ROWS*C)      x = (const float*)d_in[i];
        else if (in_sizes[i] == C*2*C)    kv_w = (const float*)d_in[i];
        else if (in_sizes[i] == T*C*C) {
            if (!qs_w) qs_w = (const float*)d_in[i];
            else       experts_w = (const float*)d_in[i];
        }
    }
    float* out = (float*)d_out;

    cudaFuncSetAttribute(attn_gemm_kernel,
                         cudaFuncAttributeMaxDynamicSharedMemorySize,
                         (int)GEMM_SMEM_BYTES);

    zero_out_kernel<<<1024, 256>>>((float4*)d_out, out_size / 4);
    qqk_kernel<<<dim3(T, B), 384>>>(x, qs_w, kv_w);
    attn_gemm_kernel<<<dim3(NF/128, B), 256, GEMM_SMEM_BYTES>>>(x);
    topk_kernel<<<B*HT, 256>>>();
    gather_scatter_kernel<<<dim3(T, H, B), 384>>>(x, experts_w, out);
    token_out_kernel<<<dim3(T, B), 384>>>(kv_w, experts_w, out);
}

// round 7
// speedup vs baseline: 1.1036x; 1.0485x over previous
#include <cuda_runtime.h>
#include <math.h>
#include <float.h>

#define B 4
#define T 8
#define NF 8192
#define C 384
#define H 12
#define TOPK 32
#define D 32
#define HT (H*T)        /* 96 */
#define ROWS (T+NF)     /* 8200 */
#define NH (NF/2)       /* 4096 per stage-1 half */
#define SCALE 0.17677669529663687f

typedef unsigned long long ull;
typedef unsigned int uint;

// ---------------- scratch (static device globals; no runtime alloc) ----------
__device__ float g_qk[B*HT*C];
__device__ float g_attn[(size_t)B*HT*NF];         // ~50MB
__device__ float g_w[B*HT*TOPK];
__device__ int   g_idx[B*HT*TOPK];
__device__ float g_fb[B*T*H*C];
__device__ ull   g_cand[B*HT][2][TOPK];           // stage-1 sorted candidates

// ---------------- helpers -----------------------------------------------------
__device__ __forceinline__ void red_add_v4(float* p, float4 v) {
    asm volatile("red.global.add.v4.f32 [%0], {%1, %2, %3, %4};"
                 :: "l"(p), "f"(v.x), "f"(v.y), "f"(v.z), "f"(v.w) : "memory");
}
__device__ __forceinline__ uint to_tf32(float f) {
    uint r;
    asm("cvt.rna.tf32.f32 %0, %1;" : "=r"(r) : "f"(f));
    return r;
}
__device__ __forceinline__ void mma_tf32(float& d0, float& d1, float& d2, float& d3,
                                         uint a0, uint a1, uint a2, uint a3,
                                         uint b0, uint b1) {
    asm("mma.sync.aligned.m16n8k8.row.col.f32.tf32.tf32.f32 "
        "{%0,%1,%2,%3}, {%4,%5,%6,%7}, {%8,%9}, {%0,%1,%2,%3};"
        : "+f"(d0), "+f"(d1), "+f"(d2), "+f"(d3)
        : "r"(a0), "r"(a1), "r"(a2), "r"(a3), "r"(b0), "r"(b1));
}

// ---------------- kernel 1: zero the output ----------------------------------
__global__ void zero_out_kernel(float4* __restrict__ out, int n4) {
    float4 z = make_float4(0.f, 0.f, 0.f, 0.f);
    for (int i = blockIdx.x * blockDim.x + threadIdx.x; i < n4;
         i += gridDim.x * blockDim.x)
        out[i] = z;
}

// ---------------- kernel 2: fused q projection + qk fold ---------------------
__global__ __launch_bounds__(384) void qqk_kernel(const float* __restrict__ x,
                                                  const float* __restrict__ qs_w,
                                                  const float* __restrict__ kv_w) {
    int b = blockIdx.y, t = blockIdx.x;
    int tid = threadIdx.x;                 // 384
    __shared__ float xs[C];
    __shared__ float qs[C];
    xs[tid] = x[((size_t)b*ROWS + t)*C + tid];
    __syncthreads();

    // 4 accumulators to break the FFMA dependency chain
    float a0 = 0.f, a1 = 0.f, a2 = 0.f, a3 = 0.f;
    const float* w = qs_w + (size_t)t*C*C + tid;
    #pragma unroll 4
    for (int c = 0; c < C; c += 4) {
        a0 += xs[c    ] * w[(size_t)(c    )*C];
        a1 += xs[c + 1] * w[(size_t)(c + 1)*C];
        a2 += xs[c + 2] * w[(size_t)(c + 2)*C];
        a3 += xs[c + 3] * w[(size_t)(c + 3)*C];
    }
    qs[tid] = (a0 + a1) + (a2 + a3);
    __syncthreads();

    const float4* kvr = (const float4*)(kv_w + (size_t)tid*(2*C));
    #pragma unroll
    for (int h = 0; h < H; h++) {
        float s = 0.f;
        #pragma unroll
        for (int d4 = 0; d4 < 8; d4++) {
            float4 kq = kvr[h*8 + d4];
            s += qs[h*D + 4*d4 + 0]*kq.x + qs[h*D + 4*d4 + 1]*kq.y
               + qs[h*D + 4*d4 + 2]*kq.z + qs[h*D + 4*d4 + 3]*kq.w;
        }
        g_qk[(((size_t)b*H + h)*T + t)*C + tid] = s * SCALE;
    }
}

// ---------------- kernel 3: attn GEMM via 3xTF32 tensor cores (FROZEN) -------
struct GemmSmem {
    float Ah[96][36];
    float Al[96][36];
    float Bh[128][36];
    float Bl[128][36];
};
#define GEMM_SMEM_BYTES sizeof(GemmSmem)

__global__ __launch_bounds__(256, 2) void attn_gemm_kernel(const float* __restrict__ x) {
    extern __shared__ __align__(16) char smem_raw[];
    GemmSmem& sm = *reinterpret_cast<GemmSmem*>(smem_raw);

    int b  = blockIdx.y;
    int n0 = blockIdx.x * 128;
    int tid = threadIdx.x;
    int wid = tid >> 5, lane = tid & 31;
    int g = lane >> 2, tig = lane & 3;
    int wm = wid & 1, wn = wid >> 1;

    const float* qk   = g_qk + (size_t)b*HT*C;
    const float* feat = x + ((size_t)b*ROWS + T)*C;

    float acc[3][4][4];
    #pragma unroll
    for (int i = 0; i < 3; i++)
        #pragma unroll
        for (int j = 0; j < 4; j++)
            #pragma unroll
            for (int r = 0; r < 4; r++) acc[i][j][r] = 0.f;

    #pragma unroll 1
    for (int chunk = 0; chunk < 12; chunk++) {
        int c0 = chunk * 32;
        __syncthreads();
        #pragma unroll
        for (int j = 0; j < 12; j++) {
            int idx = tid + j*256;
            int m = idx >> 5, k = idx & 31;
            float a = qk[(size_t)m*C + c0 + k];
            uint hb = to_tf32(a);
            float hf = __uint_as_float(hb);
            float lo = a - hf;
            sm.Ah[m][k] = hf;
            sm.Al[m][k] = __uint_as_float(to_tf32(lo));
        }
        #pragma unroll
        for (int j = 0; j < 16; j++) {
            int idx = tid + j*256;
            int n = idx >> 5, k = idx & 31;
            float v = feat[(size_t)(n0 + n)*C + c0 + k];
            uint hb = to_tf32(v);
            float hf = __uint_as_float(hb);
            float lo = v - hf;
            sm.Bh[n][k] = hf;
            sm.Bl[n][k] = __uint_as_float(to_tf32(lo));
        }
        __syncthreads();

        #pragma unroll
        for (int k8 = 0; k8 < 4; k8++) {
            int kc = k8*8 + tig;
            uint bh[4][2], bl[4][2];
            #pragma unroll
            for (int nt = 0; nt < 4; nt++) {
                int n = wn*32 + nt*8 + g;
                bh[nt][0] = __float_as_uint(sm.Bh[n][kc]);
                bh[nt][1] = __float_as_uint(sm.Bh[n][kc + 4]);
                bl[nt][0] = __float_as_uint(sm.Bl[n][kc]);
                bl[nt][1] = __float_as_uint(sm.Bl[n][kc + 4]);
            }
            #pragma unroll
            for (int mt = 0; mt < 3; mt++) {
                int m0 = wm*48 + mt*16;
                uint ah0 = __float_as_uint(sm.Ah[m0 + g    ][kc]);
                uint ah1 = __float_as_uint(sm.Ah[m0 + g + 8][kc]);
                uint ah2 = __float_as_uint(sm.Ah[m0 + g    ][kc + 4]);
                uint ah3 = __float_as_uint(sm.Ah[m0 + g + 8][kc + 4]);
                uint al0 = __float_as_uint(sm.Al[m0 + g    ][kc]);
                uint al1 = __float_as_uint(sm.Al[m0 + g + 8][kc]);
                uint al2 = __float_as_uint(sm.Al[m0 + g    ][kc + 4]);
                uint al3 = __float_as_uint(sm.Al[m0 + g + 8][kc + 4]);
                #pragma unroll
                for (int nt = 0; nt < 4; nt++) {
                    float* d = acc[mt][nt];
                    mma_tf32(d[0], d[1], d[2], d[3],
                             ah0, ah1, ah2, ah3, bh[nt][0], bh[nt][1]);
                    mma_tf32(d[0], d[1], d[2], d[3],
                             ah0, ah1, ah2, ah3, bl[nt][0], bl[nt][1]);
                    mma_tf32(d[0], d[1], d[2], d[3],
                             al0, al1, al2, al3, bh[nt][0], bh[nt][1]);
                }
            }
        }
    }

    float* outp = g_attn + (size_t)b*HT*NF;
    #pragma unroll
    for (int mt = 0; mt < 3; mt++) {
        int m0 = wm*48 + mt*16;
        #pragma unroll
        for (int nt = 0; nt < 4; nt++) {
            int nc = n0 + wn*32 + nt*8 + 2*tig;
            *(float2*)&outp[(size_t)(m0 + g    )*NF + nc] =
                make_float2(acc[mt][nt][0], acc[mt][nt][1]);
            *(float2*)&outp[(size_t)(m0 + g + 8)*NF + nc] =
                make_float2(acc[mt][nt][2], acc[mt][nt][3]);
        }
    }
}

// ---------------- top-k stage 1: exact top-32 per 4096-half -------------------
__device__ __forceinline__ unsigned enc_key(unsigned b) {
    return (b & 0x80000000u) ? ~b : (b | 0x80000000u);
}
__device__ __forceinline__ float dec_key(unsigned u) {
    unsigned b = (u & 0x80000000u) ? (u ^ 0x80000000u) : ~u;
    return __uint_as_float(b);
}

__global__ __launch_bounds__(256) void topk_stage1_kernel() {
    int blk  = blockIdx.x;                 // row*2 + half
    int row  = blk >> 1;
    int half = blk & 1;
    int base = half * NH;
    int tid = threadIdx.x;                 // 256
    int lane = tid & 31, wp = tid >> 5;
    __shared__ unsigned keys[NH];          // 16KB
    __shared__ unsigned hist[256];
    __shared__ unsigned wsuf[8];
    __shared__ unsigned sh_need, sh_prefix;
    __shared__ int cntG;
    __shared__ unsigned candK[TOPK];
    __shared__ int candI[TOPK];
    __shared__ int ri[256];

    hist[tid] = 0;
    if (tid == 0) { sh_need = TOPK; sh_prefix = 0; cntG = 0; }
    __syncthreads();

    // load + pass-0 histogram fused
    const uint4* src = (const uint4*)(g_attn + (size_t)row*NF + base);
    for (int i = tid; i < NH/4; i += 256) {
        uint4 u = src[i];
        unsigned k0 = enc_key(u.x), k1 = enc_key(u.y);
        unsigned k2 = enc_key(u.z), k3 = enc_key(u.w);
        keys[4*i+0] = k0; keys[4*i+1] = k1;
        keys[4*i+2] = k2; keys[4*i+3] = k3;
        atomicAdd(&hist[k0 >> 24], 1u);
        atomicAdd(&hist[k1 >> 24], 1u);
        atomicAdd(&hist[k2 >> 24], 1u);
        atomicAdd(&hist[k3 >> 24], 1u);
    }
    __syncthreads();

    #pragma unroll
    for (int pass = 0; pass < 4; pass++) {
        int shift = 24 - 8*pass;
        if (pass > 0) {
            hist[tid] = 0;
            __syncthreads();
            unsigned pref  = sh_prefix;
            unsigned pmask = 0xFFFFFFFFu << (shift + 8);
            for (int i = tid; i < NH; i += 256) {
                unsigned k = keys[i];
                if ((k & pmask) == pref) atomicAdd(&hist[(k >> shift) & 255], 1u);
            }
            __syncthreads();
        }

        // inclusive suffix sum over 256 bins
        unsigned v = hist[tid];
        unsigned inc = v;
        #pragma unroll
        for (int s = 1; s < 32; s <<= 1) {
            unsigned tv = __shfl_down_sync(0xffffffffu, inc, s);
            if (lane + s < 32) inc += tv;
        }
        if (lane == 0) wsuf[wp] = inc;
        __syncthreads();
        if (tid < 8) {
            unsigned tv = wsuf[tid];
            #pragma unroll
            for (int s = 1; s < 8; s <<= 1) {
                unsigned t2 = __shfl_down_sync(0xffu, tv, s);
                if (tid + s < 8) tv += t2;
            }
            wsuf[tid] = tv;
        }
        __syncthreads();
        unsigned incl = inc + (wp < 7 ? wsuf[wp + 1] : 0u);
        unsigned need = sh_need;
        unsigned excl = incl - v;
        if (incl >= need && excl < need) {
            sh_prefix = sh_prefix | ((unsigned)tid << shift);
            sh_need   = need - excl;
        }
        __syncthreads();
    }
    unsigned V = sh_prefix;
    int E = (int)sh_need;

    for (int i = tid; i < NH; i += 256) {
        unsigned k = keys[i];
        if (k > V) { int p = atomicAdd(&cntG, 1); candK[p] = k; candI[p] = base + i; }
    }
    __syncthreads();
    int G = cntG;

    int last = -1;
    for (int e = 0; e < E; e++) {
        int best = NH;
        for (int i = tid; i < NH; i += 256)
            if (keys[i] == V && i > last && i < best) best = i;
        ri[tid] = best;
        __syncthreads();
        for (int s = 128; s > 0; s >>= 1) {
            if (tid < s) ri[tid] = min(ri[tid], ri[tid + s]);
            __syncthreads();
        }
        int widx = ri[0];
        if (tid == 0) { candK[G + e] = V; candI[G + e] = base + widx; }
        last = widx;
        __syncthreads();
    }

    // rank-sort the 32 candidates (value desc, index asc), write packed sorted
    if (tid < 32) {
        unsigned k = candK[tid];
        int ix = candI[tid];
        ull ck = ((ull)k << 32) | (ull)(0xFFFFFFFFu - (unsigned)ix);
        int rank = 0;
        #pragma unroll
        for (int j = 0; j < 32; j++) {
            ull o = __shfl_sync(0xffffffffu, ck, j);
            rank += (o > ck);
        }
        g_cand[row][half][rank] = ck;
    }
}

// ---------------- top-k stage 2: merge halves + softmax -----------------------
// One warp per row. Batcher merge of two sorted 32-lists, keep top 32.
__global__ __launch_bounds__(128) void topk_merge_kernel() {
    int row  = blockIdx.x * 4 + (threadIdx.x >> 5);
    int lane = threadIdx.x & 31;

    ull a = g_cand[row][0][lane];
    ull bq = g_cand[row][1][31 - lane];
    ull c = a > bq ? a : bq;               // bitonic sequence of the top-32

    // bitonic merge -> sorted descending by lane
    #pragma unroll
    for (int st = 16; st > 0; st >>= 1) {
        ull o = __shfl_xor_sync(0xffffffffu, c, st);
        bool up = (lane & st) == 0;
        c = up ? (c > o ? c : o) : (c < o ? c : o);
    }

    float val = dec_key((unsigned)(c >> 32));
    int   idx = (int)(0xFFFFFFFFu - (unsigned)(c & 0xFFFFFFFFu));

    float m = __shfl_sync(0xffffffffu, val, 0);
    float e = expf(val - m);
    float sum = e;
    #pragma unroll
    for (int o = 16; o > 0; o >>= 1) sum += __shfl_xor_sync(0xffffffffu, sum, o);

    g_w[row*TOPK + lane]   = e / sum;
    g_idx[row*TOPK + lane] = idx;
}

// ---------------- kernel 5: fused gather (fb) + vectorized sparse scatter ----
__global__ __launch_bounds__(384) void gather_scatter_kernel(const float* __restrict__ x,
                                                             const float* __restrict__ experts_w,
                                                             float* __restrict__ out) {
    int t = blockIdx.x, h = blockIdx.y, b = blockIdx.z;
    int tid = threadIdx.x;                 // 384
    __shared__ float wsh[TOPK];
    __shared__ int   ish[TOPK];
    __shared__ float fsh[TOPK][D];
    __shared__ __align__(16) float sc[4][C];

    int row = (b*H + h)*T + t;
    if (tid < TOPK) {
        wsh[tid] = g_w[row*TOPK + tid];
        ish[tid] = g_idx[row*TOPK + tid];
    }
    __syncthreads();

    const float* feat = x + ((size_t)b*ROWS + T)*C;
    int c = tid;
    int hD = h*D;
    bool mine = (c >= hD) && (c < hD + D);
    int d = c - hD;
    float a = 0.f;
    #pragma unroll
    for (int k = 0; k < TOPK; k++) {
        float v  = feat[(size_t)ish[k]*C + c];
        float wv = wsh[k] * v;
        a += wv;
        if (mine) fsh[k][d] = wv;
    }
    g_fb[(((size_t)b*T + t)*H + h)*C + c] = a;
    __syncthreads();

    int o = tid;
    float ecol[D];
    const float* ew = experts_w + ((size_t)t*C + hD)*C + o;
    #pragma unroll
    for (int d2 = 0; d2 < D; d2++) ecol[d2] = ew[(size_t)d2*C];

    float* outb = out + ((size_t)b*ROWS + T)*C;
    int kq = tid / (C/4);
    int o4 = tid % (C/4);
    #pragma unroll 1
    for (int gI = 0; gI < TOPK/4; gI++) {
        #pragma unroll
        for (int j = 0; j < 4; j++) {
            int k = gI*4 + j;
            float s = 0.f;
            #pragma unroll
            for (int d2 = 0; d2 < D; d2++) s += fsh[k][d2] * ecol[d2];
            sc[j][o] = s;
        }
        __syncthreads();
        float4 v = *(const float4*)&sc[kq][4*o4];
        red_add_v4(&outb[(size_t)ish[gI*4 + kq]*C + 4*o4], v);
        __syncthreads();
    }
}

// ---------------- kernel 6: attn_token projection + token_out ----------------
__global__ __launch_bounds__(384) void token_out_kernel(const float* __restrict__ kv_w,
                                                        const float* __restrict__ experts_w,
                                                        float* __restrict__ out) {
    int b = blockIdx.y, t = blockIdx.x;
    int tid = threadIdx.x;                 // 384
    __shared__ float fb[H*C];              // 18KB
    __shared__ float at[C];

    const float* fbg = g_fb + ((size_t)b*T + t)*H*C;
    for (int i = tid; i < H*C; i += 384) fb[i] = fbg[i];
    __syncthreads();

    {
        int h = tid >> 5, d = tid & 31;
        const float* col = kv_w + C + h*D + d;
        float a0 = 0.f, a1 = 0.f, a2 = 0.f, a3 = 0.f;
        #pragma unroll 2
        for (int c = 0; c < C; c += 4) {
            a0 += fb[h*C + c    ] * col[(size_t)(c    )*(2*C)];
            a1 += fb[h*C + c + 1] * col[(size_t)(c + 1)*(2*C)];
            a2 += fb[h*C + c + 2] * col[(size_t)(c + 2)*(2*C)];
            a3 += fb[h*C + c + 3] * col[(size_t)(c + 3)*(2*C)];
        }
        at[h*D + d] = (a0 + a1) + (a2 + a3);
    }
    __syncthreads();
    {
        const float* ew = experts_w + (size_t)t*C*C + tid;
        float a0 = 0.f, a1 = 0.f, a2 = 0.f, a3 = 0.f;
        #pragma unroll 2
        for (int c = 0; c < C; c += 4) {
            a0 += at[c    ] * ew[(size_t)(c    )*C];
            a1 += at[c + 1] * ew[(size_t)(c + 1)*C];
            a2 += at[c + 2] * ew[(size_t)(c + 2)*C];
            a3 += at[c + 3] * ew[(size_t)(c + 3)*C];
        }
        out[((size_t)b*ROWS + t)*C + tid] = (a0 + a1) + (a2 + a3);
    }
}

// ---------------- launcher ----------------------------------------------------
extern "C" void kernel_launch(void* const* d_in, const int* in_sizes, int n_in,
                              void* d_out, int out_size) {
    const float* x = nullptr; const float* qs_w = nullptr;
    const float* kv_w = nullptr; const float* experts_w = nullptr;
    for (int i = 0; i < n_in; i++) {
        if (in_sizes[i] == B*ROWS*C)      x = (const float*)d_in[i];
        else if (in_sizes[i] == C*2*C)    kv_w = (const float*)d_in[i];
        else if (in_sizes[i] == T*C*C) {
            if (!qs_w) qs_w = (const float*)d_in[i];
            else       experts_w = (const float*)d_in[i];
        }
    }
    float* out = (float*)d_out;

    cudaFuncSetAttribute(attn_gemm_kernel,
                         cudaFuncAttributeMaxDynamicSharedMemorySize,
                         (int)GEMM_SMEM_BYTES);

    zero_out_kernel<<<1024, 256>>>((float4*)d_out, out_size / 4);
    qqk_kernel<<<dim3(T, B), 384>>>(x, qs_w, kv_w);
    attn_gemm_kernel<<<dim3(NF/128, B), 256, GEMM_SMEM_BYTES>>>(x);
    topk_stage1_kernel<<<B*HT*2, 256>>>();
    topk_merge_kernel<<<B*HT/4, 128>>>();
    gather_scatter_kernel<<<dim3(T, H, B), 384>>>(x, experts_w, out);
    token_out_kernel<<<dim3(T, B), 384>>>(kv_w, experts_w, out);
}